// round 6
// baseline (speedup 1.0000x reference)
#include <cuda_runtime.h>
#include <cstdint>

// ---------------------------------------------------------------------------
// GCN: out = segment_sum(feature[src], dst) @ W^T + b
// R6: transform-first GEMM + counting-sort by dst -> atomic-free warp-per-node
// segmented reduction (replaces 640MB of f32 RED traffic with plain stores,
// and absorbs the bias-init kernel).
// ---------------------------------------------------------------------------

#define MAX_NODES 50000
#define MAX_EDGES 625000
#define DIM 128
#define HALF_K 64
#define TILE_ROWS 64
#define SCAN_THREADS 1024

__device__ float g_feat2[(size_t)MAX_NODES * DIM];  // 25.6 MB transformed feats
__device__ int   g_src[MAX_EDGES];
__device__ int   g_dst[MAX_EDGES];
__device__ int   g_esrc[MAX_EDGES];                 // src ids sorted by dst
__device__ int   g_count[MAX_NODES];
__device__ int   g_off[MAX_NODES + 1];
__device__ int   g_cursor[MAX_NODES];
__device__ int   g_idx_is_64;

// ---------------------------------------------------------------------------
// Zero per-call state (graph replays re-run everything).
// ---------------------------------------------------------------------------
__global__ __launch_bounds__(256) void zero_counts_kernel()
{
    int i = blockIdx.x * blockDim.x + threadIdx.x;
    if (i < MAX_NODES) g_count[i] = 0;
}

// ---------------------------------------------------------------------------
// Detect index width: int64 => odd 32-bit words (high words) all zero.
// ---------------------------------------------------------------------------
__global__ void detect_idx_width_kernel(const int* __restrict__ a,
                                        const int* __restrict__ b)
{
    int all_zero = 1;
    for (int i = 1; i < 2048; i += 2) {
        if (a[i] != 0 || b[i] != 0) { all_zero = 0; break; }
    }
    g_idx_is_64 = all_zero;
}

// ---------------------------------------------------------------------------
// Normalize indices to int scratch + histogram of dst.
// ---------------------------------------------------------------------------
__global__ __launch_bounds__(256) void normalize_hist_kernel(
    const int* __restrict__ src_words, const int* __restrict__ dst_words, int E)
{
    int i = blockIdx.x * blockDim.x + threadIdx.x;
    if (i >= E) return;
    int is64 = g_idx_is_64;
    int s = is64 ? src_words[2 * i] : src_words[i];
    int d = is64 ? dst_words[2 * i] : dst_words[i];
    g_src[i] = s;
    g_dst[i] = d;
    if ((unsigned)d < MAX_NODES && (unsigned)s < MAX_NODES)
        atomicAdd(&g_count[d], 1);
}

// ---------------------------------------------------------------------------
// Single-CTA exclusive scan of g_count[50000] -> g_off / g_cursor.
// 1024 threads x 49 items serial + Hillis-Steele block scan.
// ---------------------------------------------------------------------------
__global__ __launch_bounds__(SCAN_THREADS) void scan_kernel()
{
    __shared__ int sp[SCAN_THREADS];
    const int per = (MAX_NODES + SCAN_THREADS - 1) / SCAN_THREADS;  // 49
    int t = threadIdx.x;
    int lo = t * per;
    int hi = min(lo + per, MAX_NODES);

    int local = 0;
    for (int i = lo; i < hi; i++) local += g_count[i];
    sp[t] = local;
    __syncthreads();

    // inclusive Hillis-Steele over 1024 partials
    for (int d = 1; d < SCAN_THREADS; d <<= 1) {
        int v = (t >= d) ? sp[t - d] : 0;
        __syncthreads();
        sp[t] += v;
        __syncthreads();
    }
    int running = sp[t] - local;  // exclusive prefix of this thread's chunk

    for (int i = lo; i < hi; i++) {
        g_off[i] = running;
        g_cursor[i] = running;
        running += g_count[i];
    }
    if (t == SCAN_THREADS - 1) g_off[MAX_NODES] = running;
}

// ---------------------------------------------------------------------------
// Bucket fill: place each edge's src into its dst bucket.
// ---------------------------------------------------------------------------
__global__ __launch_bounds__(256) void fill_kernel(int E)
{
    int i = blockIdx.x * blockDim.x + threadIdx.x;
    if (i >= E) return;
    int s = g_src[i];
    int d = g_dst[i];
    if ((unsigned)d >= MAX_NODES || (unsigned)s >= MAX_NODES) return;
    int pos = atomicAdd(&g_cursor[d], 1);
    g_esrc[pos] = s;
}

// ---------------------------------------------------------------------------
// Kernel A: feat2[n][k] = sum_c feature[n][c] * W[k][c]
// 256 threads, 64 rows/CTA, K split into two 64-channel passes, 48KB smem.
// ---------------------------------------------------------------------------
__global__ __launch_bounds__(256) void gemm_kernel(
    const float* __restrict__ feature, const float* __restrict__ W, int N)
{
    __shared__ float sW[HALF_K * DIM];      // sW[cl*128 + k] = W[k][h*64+cl]
    __shared__ float sF[TILE_ROWS * HALF_K];

    int tid = threadIdx.x;
    int warp = tid >> 5, lane = tid & 31;
    int row0 = blockIdx.x * TILE_ROWS;

    float4 acc0 = make_float4(0.f, 0.f, 0.f, 0.f);
    float4 acc1 = acc0, acc2 = acc0, acc3 = acc0;
    float4 acc4 = acc0, acc5 = acc0, acc6 = acc0, acc7 = acc0;

    #pragma unroll
    for (int h = 0; h < 2; h++) {
        if (h) __syncthreads();

        for (int i = tid; i < DIM * HALF_K; i += 256) {
            int k = i >> 6, cl = i & 63;
            sW[cl * DIM + k] = W[k * DIM + h * HALF_K + cl];
        }
        for (int i = tid; i < TILE_ROWS * (HALF_K / 4); i += 256) {
            int r = i >> 4, c4 = i & 15;
            int gr = row0 + r;
            float4 v = make_float4(0.f, 0.f, 0.f, 0.f);
            if (gr < N)
                v = reinterpret_cast<const float4*>(feature + (size_t)gr * DIM + h * HALF_K)[c4];
            reinterpret_cast<float4*>(sF + r * HALF_K)[c4] = v;
        }
        __syncthreads();

        int r0 = warp * 8;
        #pragma unroll 4
        for (int c = 0; c < HALF_K; c++) {
            float4 wv = reinterpret_cast<const float4*>(sW + c * DIM)[lane];
            float f0 = sF[(r0 + 0) * HALF_K + c];
            float f1 = sF[(r0 + 1) * HALF_K + c];
            float f2 = sF[(r0 + 2) * HALF_K + c];
            float f3 = sF[(r0 + 3) * HALF_K + c];
            acc0.x += f0 * wv.x; acc0.y += f0 * wv.y; acc0.z += f0 * wv.z; acc0.w += f0 * wv.w;
            acc1.x += f1 * wv.x; acc1.y += f1 * wv.y; acc1.z += f1 * wv.z; acc1.w += f1 * wv.w;
            acc2.x += f2 * wv.x; acc2.y += f2 * wv.y; acc2.z += f2 * wv.z; acc2.w += f2 * wv.w;
            acc3.x += f3 * wv.x; acc3.y += f3 * wv.y; acc3.z += f3 * wv.z; acc3.w += f3 * wv.w;
            float f4 = sF[(r0 + 4) * HALF_K + c];
            float f5 = sF[(r0 + 5) * HALF_K + c];
            float f6 = sF[(r0 + 6) * HALF_K + c];
            float f7 = sF[(r0 + 7) * HALF_K + c];
            acc4.x += f4 * wv.x; acc4.y += f4 * wv.y; acc4.z += f4 * wv.z; acc4.w += f4 * wv.w;
            acc5.x += f5 * wv.x; acc5.y += f5 * wv.y; acc5.z += f5 * wv.z; acc5.w += f5 * wv.w;
            acc6.x += f6 * wv.x; acc6.y += f6 * wv.y; acc6.z += f6 * wv.z; acc6.w += f6 * wv.w;
            acc7.x += f7 * wv.x; acc7.y += f7 * wv.y; acc7.z += f7 * wv.z; acc7.w += f7 * wv.w;
        }
    }

    int r0 = warp * 8;
    float4* o = reinterpret_cast<float4*>(g_feat2 + (size_t)(row0 + r0) * DIM);
    if (row0 + r0 + 0 < N) (o +   0)[lane] = acc0;
    if (row0 + r0 + 1 < N) (o +  32)[lane] = acc1;
    if (row0 + r0 + 2 < N) (o +  64)[lane] = acc2;
    if (row0 + r0 + 3 < N) (o +  96)[lane] = acc3;
    if (row0 + r0 + 4 < N) (o + 128)[lane] = acc4;
    if (row0 + r0 + 5 < N) (o + 160)[lane] = acc5;
    if (row0 + r0 + 6 < N) (o + 192)[lane] = acc6;
    if (row0 + r0 + 7 < N) (o + 224)[lane] = acc7;
}

// ---------------------------------------------------------------------------
// Reduce: one warp per node. Walk the node's sorted edge list, accumulate
// feat2[src] rows (float4 per lane), write out[n] = acc + b once. No atomics.
// ---------------------------------------------------------------------------
__global__ __launch_bounds__(256) void reduce_kernel(
    const float* __restrict__ b, float* __restrict__ out, int N)
{
    int n = (blockIdx.x * blockDim.x + threadIdx.x) >> 5;
    int lane = threadIdx.x & 31;
    if (n >= N) return;

    int begin = g_off[n];
    int end   = g_off[n + 1];

    float4 acc = reinterpret_cast<const float4*>(b)[lane];  // bias seed
    for (int e = begin; e < end; e++) {
        int s = g_esrc[e];  // lane-uniform broadcast load
        float4 v = reinterpret_cast<const float4*>(g_feat2 + (size_t)s * DIM)[lane];
        acc.x += v.x; acc.y += v.y; acc.z += v.z; acc.w += v.w;
    }
    reinterpret_cast<float4*>(out + (size_t)n * DIM)[lane] = acc;
}

// ---------------------------------------------------------------------------
extern "C" void kernel_launch(void* const* d_in, const int* in_sizes, int n_in,
                              void* d_out, int out_size)
{
    // Identify inputs BY SIZE (robust to ordering and width reporting).
    const float* feature = nullptr;
    const float* W = nullptr;
    const float* b = nullptr;
    const int*   idx_words[2] = {nullptr, nullptr};
    int n_idx = 0;

    for (int i = 0; i < n_in; i++) {
        long long s = in_sizes[i];
        if (s == 128 || s == 512) {
            b = (const float*)d_in[i];
        } else if (s == 16384 || s == 65536) {
            W = (const float*)d_in[i];
        } else if (s == 625000 || s == 1250000 || s == 2500000 || s == 5000000) {
            if (n_idx < 2) idx_words[n_idx++] = (const int*)d_in[i];
        } else if (s == 6400000 || s == 25600000) {
            feature = (const float*)d_in[i];
        }
    }
    if (!feature || !W || !b || n_idx < 2) {  // positional fallback
        feature      = (const float*)d_in[0];
        idx_words[0] = (const int*)d_in[1];
        idx_words[1] = (const int*)d_in[2];
        W            = (const float*)d_in[3];
        b            = (const float*)d_in[4];
    }

    const int N = MAX_NODES;
    const int E = MAX_EDGES;
    float* out = (float*)d_out;

    // Sort chain
    zero_counts_kernel<<<(N + 255) / 256, 256>>>();
    detect_idx_width_kernel<<<1, 1>>>(idx_words[0], idx_words[1]);
    normalize_hist_kernel<<<(E + 255) / 256, 256>>>(idx_words[0], idx_words[1], E);
    scan_kernel<<<1, SCAN_THREADS>>>();
    fill_kernel<<<(E + 255) / 256, 256>>>(E);
    // Transform (independent of sort chain; stream order is fine)
    gemm_kernel<<<(N + TILE_ROWS - 1) / TILE_ROWS, 256>>>(feature, W, N);
    // Atomic-free segmented reduction + bias
    reduce_kernel<<<(N * 32 + 255) / 256, 256>>>(b, out, N);
}

// round 8
// speedup vs baseline: 1.4496x; 1.4496x over previous
#include <cuda_runtime.h>
#include <cstdint>

// ---------------------------------------------------------------------------
// GCN: out = segment_sum(feature[src], dst) @ W^T + b
// R8 = R7 resubmission (R7 died to container-infra flake before running).
// transform-first GEMM + counting-sort by dst -> atomic-free warp-per-node
// segmented reduction. Multi-CTA 3-stage scan replaces R6's 83us 1-CTA scan;
// width-detect parallelized to one warp.
// ---------------------------------------------------------------------------

#define MAX_NODES 50000
#define MAX_EDGES 625000
#define DIM 128
#define HALF_K 64
#define TILE_ROWS 64
#define SCAN_BLK 256
#define NUM_SCAN_BLOCKS ((MAX_NODES + SCAN_BLK - 1) / SCAN_BLK)  // 196

__device__ float g_feat2[(size_t)MAX_NODES * DIM];  // 25.6 MB transformed feats
__device__ int   g_src[MAX_EDGES];
__device__ int   g_dst[MAX_EDGES];
__device__ int   g_esrc[MAX_EDGES];                 // src ids sorted by dst
__device__ int   g_count[MAX_NODES];
__device__ int   g_off[MAX_NODES + 1];
__device__ int   g_cursor[MAX_NODES];
__device__ int   g_bsum[NUM_SCAN_BLOCKS];
__device__ int   g_boff[NUM_SCAN_BLOCKS];
__device__ int   g_idx_is_64;

// ---------------------------------------------------------------------------
// Zero per-call state (graph replays re-run everything).
// ---------------------------------------------------------------------------
__global__ __launch_bounds__(256) void zero_counts_kernel()
{
    int i = blockIdx.x * blockDim.x + threadIdx.x;
    if (i < MAX_NODES) g_count[i] = 0;
}

// ---------------------------------------------------------------------------
// Detect index width (int64 => odd 32-bit words all zero). One warp, strided
// lanes, ballot reduce.
// ---------------------------------------------------------------------------
__global__ void detect_idx_width_kernel(const int* __restrict__ a,
                                        const int* __restrict__ b)
{
    int lane = threadIdx.x;
    int nonzero = 0;
    for (int i = 2 * lane + 1; i < 2048; i += 64)
        if (a[i] != 0 || b[i] != 0) nonzero = 1;
    unsigned any = __any_sync(0xFFFFFFFFu, nonzero);
    if (lane == 0) g_idx_is_64 = any ? 0 : 1;
}

// ---------------------------------------------------------------------------
// Normalize indices to int scratch + histogram of dst.
// ---------------------------------------------------------------------------
__global__ __launch_bounds__(256) void normalize_hist_kernel(
    const int* __restrict__ src_words, const int* __restrict__ dst_words, int E)
{
    int i = blockIdx.x * blockDim.x + threadIdx.x;
    if (i >= E) return;
    int is64 = g_idx_is_64;
    int s = is64 ? src_words[2 * i] : src_words[i];
    int d = is64 ? dst_words[2 * i] : dst_words[i];
    g_src[i] = s;
    g_dst[i] = d;
    if ((unsigned)d < MAX_NODES && (unsigned)s < MAX_NODES)
        atomicAdd(&g_count[d], 1);
}

// ---------------------------------------------------------------------------
// Scan stage 1: per-block exclusive scan of 256 counts; block sum to g_bsum.
// ---------------------------------------------------------------------------
__global__ __launch_bounds__(SCAN_BLK) void scan1_kernel()
{
    __shared__ int sp[SCAN_BLK];
    int t = threadIdx.x;
    int i = blockIdx.x * SCAN_BLK + t;
    int v = (i < MAX_NODES) ? g_count[i] : 0;
    sp[t] = v;
    __syncthreads();
    // Hillis-Steele inclusive over 256
    #pragma unroll
    for (int d = 1; d < SCAN_BLK; d <<= 1) {
        int u = (t >= d) ? sp[t - d] : 0;
        __syncthreads();
        sp[t] += u;
        __syncthreads();
    }
    if (i < MAX_NODES) g_off[i] = sp[t] - v;           // local exclusive
    if (t == SCAN_BLK - 1) g_bsum[blockIdx.x] = sp[t]; // block total
}

// ---------------------------------------------------------------------------
// Scan stage 2: single small CTA scans the 196 block sums.
// ---------------------------------------------------------------------------
__global__ __launch_bounds__(SCAN_BLK) void scan2_kernel()
{
    __shared__ int sp[SCAN_BLK];
    int t = threadIdx.x;
    int v = (t < NUM_SCAN_BLOCKS) ? g_bsum[t] : 0;
    sp[t] = v;
    __syncthreads();
    #pragma unroll
    for (int d = 1; d < SCAN_BLK; d <<= 1) {
        int u = (t >= d) ? sp[t - d] : 0;
        __syncthreads();
        sp[t] += u;
        __syncthreads();
    }
    if (t < NUM_SCAN_BLOCKS) g_boff[t] = sp[t] - v;    // exclusive
    if (t == SCAN_BLK - 1) g_off[MAX_NODES] = sp[t];   // grand total
}

// ---------------------------------------------------------------------------
// Scan stage 3: add block offsets; materialize g_off and g_cursor.
// ---------------------------------------------------------------------------
__global__ __launch_bounds__(256) void scan3_kernel()
{
    int i = blockIdx.x * blockDim.x + threadIdx.x;
    if (i >= MAX_NODES) return;
    int v = g_off[i] + g_boff[i >> 8];
    g_off[i] = v;
    g_cursor[i] = v;
}

// ---------------------------------------------------------------------------
// Bucket fill: place each edge's src into its dst bucket.
// ---------------------------------------------------------------------------
__global__ __launch_bounds__(256) void fill_kernel(int E)
{
    int i = blockIdx.x * blockDim.x + threadIdx.x;
    if (i >= E) return;
    int s = g_src[i];
    int d = g_dst[i];
    if ((unsigned)d >= MAX_NODES || (unsigned)s >= MAX_NODES) return;
    int pos = atomicAdd(&g_cursor[d], 1);
    g_esrc[pos] = s;
}

// ---------------------------------------------------------------------------
// Kernel A: feat2[n][k] = sum_c feature[n][c] * W[k][c]
// 256 threads, 64 rows/CTA, K split into two 64-channel passes, 48KB smem.
// ---------------------------------------------------------------------------
__global__ __launch_bounds__(256) void gemm_kernel(
    const float* __restrict__ feature, const float* __restrict__ W, int N)
{
    __shared__ float sW[HALF_K * DIM];      // sW[cl*128 + k] = W[k][h*64+cl]
    __shared__ float sF[TILE_ROWS * HALF_K];

    int tid = threadIdx.x;
    int warp = tid >> 5, lane = tid & 31;
    int row0 = blockIdx.x * TILE_ROWS;

    float4 acc0 = make_float4(0.f, 0.f, 0.f, 0.f);
    float4 acc1 = acc0, acc2 = acc0, acc3 = acc0;
    float4 acc4 = acc0, acc5 = acc0, acc6 = acc0, acc7 = acc0;

    #pragma unroll
    for (int h = 0; h < 2; h++) {
        if (h) __syncthreads();

        for (int i = tid; i < DIM * HALF_K; i += 256) {
            int k = i >> 6, cl = i & 63;
            sW[cl * DIM + k] = W[k * DIM + h * HALF_K + cl];
        }
        for (int i = tid; i < TILE_ROWS * (HALF_K / 4); i += 256) {
            int r = i >> 4, c4 = i & 15;
            int gr = row0 + r;
            float4 v = make_float4(0.f, 0.f, 0.f, 0.f);
            if (gr < N)
                v = reinterpret_cast<const float4*>(feature + (size_t)gr * DIM + h * HALF_K)[c4];
            reinterpret_cast<float4*>(sF + r * HALF_K)[c4] = v;
        }
        __syncthreads();

        int r0 = warp * 8;
        #pragma unroll 4
        for (int c = 0; c < HALF_K; c++) {
            float4 wv = reinterpret_cast<const float4*>(sW + c * DIM)[lane];
            float f0 = sF[(r0 + 0) * HALF_K + c];
            float f1 = sF[(r0 + 1) * HALF_K + c];
            float f2 = sF[(r0 + 2) * HALF_K + c];
            float f3 = sF[(r0 + 3) * HALF_K + c];
            acc0.x += f0 * wv.x; acc0.y += f0 * wv.y; acc0.z += f0 * wv.z; acc0.w += f0 * wv.w;
            acc1.x += f1 * wv.x; acc1.y += f1 * wv.y; acc1.z += f1 * wv.z; acc1.w += f1 * wv.w;
            acc2.x += f2 * wv.x; acc2.y += f2 * wv.y; acc2.z += f2 * wv.z; acc2.w += f2 * wv.w;
            acc3.x += f3 * wv.x; acc3.y += f3 * wv.y; acc3.z += f3 * wv.z; acc3.w += f3 * wv.w;
            float f4 = sF[(r0 + 4) * HALF_K + c];
            float f5 = sF[(r0 + 5) * HALF_K + c];
            float f6 = sF[(r0 + 6) * HALF_K + c];
            float f7 = sF[(r0 + 7) * HALF_K + c];
            acc4.x += f4 * wv.x; acc4.y += f4 * wv.y; acc4.z += f4 * wv.z; acc4.w += f4 * wv.w;
            acc5.x += f5 * wv.x; acc5.y += f5 * wv.y; acc5.z += f5 * wv.z; acc5.w += f5 * wv.w;
            acc6.x += f6 * wv.x; acc6.y += f6 * wv.y; acc6.z += f6 * wv.z; acc6.w += f6 * wv.w;
            acc7.x += f7 * wv.x; acc7.y += f7 * wv.y; acc7.z += f7 * wv.z; acc7.w += f7 * wv.w;
        }
    }

    int r0 = warp * 8;
    float4* o = reinterpret_cast<float4*>(g_feat2 + (size_t)(row0 + r0) * DIM);
    if (row0 + r0 + 0 < N) (o +   0)[lane] = acc0;
    if (row0 + r0 + 1 < N) (o +  32)[lane] = acc1;
    if (row0 + r0 + 2 < N) (o +  64)[lane] = acc2;
    if (row0 + r0 + 3 < N) (o +  96)[lane] = acc3;
    if (row0 + r0 + 4 < N) (o + 128)[lane] = acc4;
    if (row0 + r0 + 5 < N) (o + 160)[lane] = acc5;
    if (row0 + r0 + 6 < N) (o + 192)[lane] = acc6;
    if (row0 + r0 + 7 < N) (o + 224)[lane] = acc7;
}

// ---------------------------------------------------------------------------
// Reduce: one warp per node. Walk the node's sorted edge list, accumulate
// feat2[src] rows (float4 per lane), write out[n] = acc + b once. No atomics.
// ---------------------------------------------------------------------------
__global__ __launch_bounds__(256) void reduce_kernel(
    const float* __restrict__ b, float* __restrict__ out, int N)
{
    int n = (blockIdx.x * blockDim.x + threadIdx.x) >> 5;
    int lane = threadIdx.x & 31;
    if (n >= N) return;

    int begin = g_off[n];
    int end   = g_off[n + 1];

    float4 acc = reinterpret_cast<const float4*>(b)[lane];  // bias seed
    for (int e = begin; e < end; e++) {
        int s = g_esrc[e];  // lane-uniform broadcast load
        float4 v = reinterpret_cast<const float4*>(g_feat2 + (size_t)s * DIM)[lane];
        acc.x += v.x; acc.y += v.y; acc.z += v.z; acc.w += v.w;
    }
    reinterpret_cast<float4*>(out + (size_t)n * DIM)[lane] = acc;
}

// ---------------------------------------------------------------------------
extern "C" void kernel_launch(void* const* d_in, const int* in_sizes, int n_in,
                              void* d_out, int out_size)
{
    // Identify inputs BY SIZE (robust to ordering and width reporting).
    const float* feature = nullptr;
    const float* W = nullptr;
    const float* b = nullptr;
    const int*   idx_words[2] = {nullptr, nullptr};
    int n_idx = 0;

    for (int i = 0; i < n_in; i++) {
        long long s = in_sizes[i];
        if (s == 128 || s == 512) {
            b = (const float*)d_in[i];
        } else if (s == 16384 || s == 65536) {
            W = (const float*)d_in[i];
        } else if (s == 625000 || s == 1250000 || s == 2500000 || s == 5000000) {
            if (n_idx < 2) idx_words[n_idx++] = (const int*)d_in[i];
        } else if (s == 6400000 || s == 25600000) {
            feature = (const float*)d_in[i];
        }
    }
    if (!feature || !W || !b || n_idx < 2) {  // positional fallback
        feature      = (const float*)d_in[0];
        idx_words[0] = (const int*)d_in[1];
        idx_words[1] = (const int*)d_in[2];
        W            = (const float*)d_in[3];
        b            = (const float*)d_in[4];
    }

    const int N = MAX_NODES;
    const int E = MAX_EDGES;
    float* out = (float*)d_out;

    // Sort chain
    zero_counts_kernel<<<(N + 255) / 256, 256>>>();
    detect_idx_width_kernel<<<1, 32>>>(idx_words[0], idx_words[1]);
    normalize_hist_kernel<<<(E + 255) / 256, 256>>>(idx_words[0], idx_words[1], E);
    scan1_kernel<<<NUM_SCAN_BLOCKS, SCAN_BLK>>>();
    scan2_kernel<<<1, SCAN_BLK>>>();
    scan3_kernel<<<(N + 255) / 256, 256>>>();
    fill_kernel<<<(E + 255) / 256, 256>>>(E);
    // Transform (independent of sort chain; stream order serializes)
    gemm_kernel<<<(N + TILE_ROWS - 1) / TILE_ROWS, 256>>>(feature, W, N);
    // Atomic-free segmented reduction + bias
    reduce_kernel<<<(N * 32 + 255) / 256, 256>>>(b, out, N);
}

// round 9
// speedup vs baseline: 1.5280x; 1.0541x over previous
#include <cuda_runtime.h>
#include <cstdint>

// ---------------------------------------------------------------------------
// GCN: out = segment_sum(feature[src], dst) @ W^T + b
// R9: counting-sort pipeline (validated R8) +
//   - GEMM inner loop moved to packed fma.rn.f32x2 (2x fp32 throughput;
//     scalar FFMA floor was the binding limit at ~48us)
//   - reduce kernel 4-way unrolled for MLP (was serial L2-latency chain)
// ---------------------------------------------------------------------------

#define MAX_NODES 50000
#define MAX_EDGES 625000
#define DIM 128
#define HALF_K 64
#define TILE_ROWS 64
#define SCAN_BLK 256
#define NUM_SCAN_BLOCKS ((MAX_NODES + SCAN_BLK - 1) / SCAN_BLK)  // 196

__device__ float g_feat2[(size_t)MAX_NODES * DIM];  // 25.6 MB transformed feats
__device__ int   g_src[MAX_EDGES];
__device__ int   g_dst[MAX_EDGES];
__device__ int   g_esrc[MAX_EDGES];                 // src ids sorted by dst
__device__ int   g_count[MAX_NODES];
__device__ int   g_off[MAX_NODES + 1];
__device__ int   g_cursor[MAX_NODES];
__device__ int   g_bsum[NUM_SCAN_BLOCKS];
__device__ int   g_boff[NUM_SCAN_BLOCKS];
__device__ int   g_idx_is_64;

// packed f32x2 FMA: d = a*b + c on both 32-bit halves (Blackwell)
#define FMA2(d, a, b, c) \
    asm("fma.rn.f32x2 %0, %1, %2, %3;" : "=l"(d) : "l"(a), "l"(b), "l"(c))
// pack scalar float into both halves of a b64
#define PACK2(d, f) \
    asm("mov.b64 %0, {%1, %1};" : "=l"(d) : "r"(__float_as_uint(f)))

// ---------------------------------------------------------------------------
__global__ __launch_bounds__(256) void zero_counts_kernel()
{
    int i = blockIdx.x * blockDim.x + threadIdx.x;
    if (i < MAX_NODES) g_count[i] = 0;
}

// ---------------------------------------------------------------------------
// Detect index width (int64 => odd 32-bit words all zero). One warp.
// ---------------------------------------------------------------------------
__global__ void detect_idx_width_kernel(const int* __restrict__ a,
                                        const int* __restrict__ b)
{
    int lane = threadIdx.x;
    int nonzero = 0;
    for (int i = 2 * lane + 1; i < 2048; i += 64)
        if (a[i] != 0 || b[i] != 0) nonzero = 1;
    unsigned any = __any_sync(0xFFFFFFFFu, nonzero);
    if (lane == 0) g_idx_is_64 = any ? 0 : 1;
}

// ---------------------------------------------------------------------------
// Normalize indices to int scratch + histogram of dst.
// ---------------------------------------------------------------------------
__global__ __launch_bounds__(256) void normalize_hist_kernel(
    const int* __restrict__ src_words, const int* __restrict__ dst_words, int E)
{
    int i = blockIdx.x * blockDim.x + threadIdx.x;
    if (i >= E) return;
    int is64 = g_idx_is_64;
    int s = is64 ? src_words[2 * i] : src_words[i];
    int d = is64 ? dst_words[2 * i] : dst_words[i];
    g_src[i] = s;
    g_dst[i] = d;
    if ((unsigned)d < MAX_NODES && (unsigned)s < MAX_NODES)
        atomicAdd(&g_count[d], 1);
}

// ---------------------------------------------------------------------------
// Scan stage 1: per-block exclusive scan of 256 counts; block sum to g_bsum.
// ---------------------------------------------------------------------------
__global__ __launch_bounds__(SCAN_BLK) void scan1_kernel()
{
    __shared__ int sp[SCAN_BLK];
    int t = threadIdx.x;
    int i = blockIdx.x * SCAN_BLK + t;
    int v = (i < MAX_NODES) ? g_count[i] : 0;
    sp[t] = v;
    __syncthreads();
    #pragma unroll
    for (int d = 1; d < SCAN_BLK; d <<= 1) {
        int u = (t >= d) ? sp[t - d] : 0;
        __syncthreads();
        sp[t] += u;
        __syncthreads();
    }
    if (i < MAX_NODES) g_off[i] = sp[t] - v;
    if (t == SCAN_BLK - 1) g_bsum[blockIdx.x] = sp[t];
}

// ---------------------------------------------------------------------------
// Scan stage 2: single CTA scans the 196 block sums.
// ---------------------------------------------------------------------------
__global__ __launch_bounds__(SCAN_BLK) void scan2_kernel()
{
    __shared__ int sp[SCAN_BLK];
    int t = threadIdx.x;
    int v = (t < NUM_SCAN_BLOCKS) ? g_bsum[t] : 0;
    sp[t] = v;
    __syncthreads();
    #pragma unroll
    for (int d = 1; d < SCAN_BLK; d <<= 1) {
        int u = (t >= d) ? sp[t - d] : 0;
        __syncthreads();
        sp[t] += u;
        __syncthreads();
    }
    if (t < NUM_SCAN_BLOCKS) g_boff[t] = sp[t] - v;
    if (t == SCAN_BLK - 1) g_off[MAX_NODES] = sp[t];
}

// ---------------------------------------------------------------------------
// Scan stage 3: add block offsets; materialize g_off and g_cursor.
// ---------------------------------------------------------------------------
__global__ __launch_bounds__(256) void scan3_kernel()
{
    int i = blockIdx.x * blockDim.x + threadIdx.x;
    if (i >= MAX_NODES) return;
    int v = g_off[i] + g_boff[i >> 8];
    g_off[i] = v;
    g_cursor[i] = v;
}

// ---------------------------------------------------------------------------
// Bucket fill: place each edge's src into its dst bucket.
// ---------------------------------------------------------------------------
__global__ __launch_bounds__(256) void fill_kernel(int E)
{
    int i = blockIdx.x * blockDim.x + threadIdx.x;
    if (i >= E) return;
    int s = g_src[i];
    int d = g_dst[i];
    if ((unsigned)d >= MAX_NODES || (unsigned)s >= MAX_NODES) return;
    int pos = atomicAdd(&g_cursor[d], 1);
    g_esrc[pos] = s;
}

// ---------------------------------------------------------------------------
// Kernel A: feat2[n][k] = sum_c feature[n][c] * W[k][c]
// 256 threads, 64 rows/CTA, K split into two 64-channel passes, 48KB smem.
// Inner loop uses packed fma.rn.f32x2: per c-iter per warp
//   1 LDS.128 (W pair-vector) + 8 broadcast LDS + 8 PACK (alu) + 16 FFMA2.
// ---------------------------------------------------------------------------
__global__ __launch_bounds__(256) void gemm_kernel(
    const float* __restrict__ feature, const float* __restrict__ W, int N)
{
    __shared__ float sW[HALF_K * DIM];      // sW[cl*128 + k] = W[k][h*64+cl]
    __shared__ float sF[TILE_ROWS * HALF_K];

    int tid = threadIdx.x;
    int warp = tid >> 5, lane = tid & 31;
    int row0 = blockIdx.x * TILE_ROWS;

    // 8 rows x 4 outputs, stored as 8 x 2 packed f32x2 accumulators
    unsigned long long accA[8] = {0, 0, 0, 0, 0, 0, 0, 0};  // (k0,k1)
    unsigned long long accB[8] = {0, 0, 0, 0, 0, 0, 0, 0};  // (k2,k3)

    #pragma unroll
    for (int h = 0; h < 2; h++) {
        if (h) __syncthreads();

        for (int i = tid; i < DIM * HALF_K; i += 256) {
            int k = i >> 6, cl = i & 63;
            sW[cl * DIM + k] = W[k * DIM + h * HALF_K + cl];
        }
        for (int i = tid; i < TILE_ROWS * (HALF_K / 4); i += 256) {
            int r = i >> 4, c4 = i & 15;
            int gr = row0 + r;
            float4 v = make_float4(0.f, 0.f, 0.f, 0.f);
            if (gr < N)
                v = reinterpret_cast<const float4*>(feature + (size_t)gr * DIM + h * HALF_K)[c4];
            reinterpret_cast<float4*>(sF + r * HALF_K)[c4] = v;
        }
        __syncthreads();

        int r0 = warp * 8;
        #pragma unroll 4
        for (int c = 0; c < HALF_K; c++) {
            // W column for this lane's 4 k's, as two packed f32x2
            ulonglong2 wv = reinterpret_cast<const ulonglong2*>(sW + c * DIM)[lane];
            #pragma unroll
            for (int r = 0; r < 8; r++) {
                float f = sF[(r0 + r) * HALF_K + c];
                unsigned long long fp;
                PACK2(fp, f);
                FMA2(accA[r], fp, wv.x, accA[r]);
                FMA2(accB[r], fp, wv.y, accB[r]);
            }
        }
    }

    int r0 = warp * 8;
    #pragma unroll
    for (int r = 0; r < 8; r++) {
        int gr = row0 + r0 + r;
        if (gr < N) {
            ulonglong2 o;
            o.x = accA[r];
            o.y = accB[r];
            reinterpret_cast<ulonglong2*>(g_feat2 + (size_t)gr * DIM)[lane] = o;
        }
    }
}

// ---------------------------------------------------------------------------
// Reduce: one warp per node, 4-way unrolled edge walk for MLP.
// acc = b; acc += feat2[src_e] for each edge; single store. No atomics.
// ---------------------------------------------------------------------------
__global__ __launch_bounds__(256) void reduce_kernel(
    const float* __restrict__ b, float* __restrict__ out, int N)
{
    int n = (blockIdx.x * blockDim.x + threadIdx.x) >> 5;
    int lane = threadIdx.x & 31;
    if (n >= N) return;

    int e   = g_off[n];
    int end = g_off[n + 1];

    float4 acc = reinterpret_cast<const float4*>(b)[lane];  // bias seed

    for (; e + 4 <= end; e += 4) {
        int s0 = g_esrc[e + 0];
        int s1 = g_esrc[e + 1];
        int s2 = g_esrc[e + 2];
        int s3 = g_esrc[e + 3];
        float4 v0 = reinterpret_cast<const float4*>(g_feat2 + (size_t)s0 * DIM)[lane];
        float4 v1 = reinterpret_cast<const float4*>(g_feat2 + (size_t)s1 * DIM)[lane];
        float4 v2 = reinterpret_cast<const float4*>(g_feat2 + (size_t)s2 * DIM)[lane];
        float4 v3 = reinterpret_cast<const float4*>(g_feat2 + (size_t)s3 * DIM)[lane];
        acc.x += v0.x; acc.y += v0.y; acc.z += v0.z; acc.w += v0.w;
        acc.x += v1.x; acc.y += v1.y; acc.z += v1.z; acc.w += v1.w;
        acc.x += v2.x; acc.y += v2.y; acc.z += v2.z; acc.w += v2.w;
        acc.x += v3.x; acc.y += v3.y; acc.z += v3.z; acc.w += v3.w;
    }
    for (; e < end; e++) {
        int s = g_esrc[e];
        float4 v = reinterpret_cast<const float4*>(g_feat2 + (size_t)s * DIM)[lane];
        acc.x += v.x; acc.y += v.y; acc.z += v.z; acc.w += v.w;
    }
    reinterpret_cast<float4*>(out + (size_t)n * DIM)[lane] = acc;
}

// ---------------------------------------------------------------------------
extern "C" void kernel_launch(void* const* d_in, const int* in_sizes, int n_in,
                              void* d_out, int out_size)
{
    // Identify inputs BY SIZE (robust to ordering and width reporting).
    const float* feature = nullptr;
    const float* W = nullptr;
    const float* b = nullptr;
    const int*   idx_words[2] = {nullptr, nullptr};
    int n_idx = 0;

    for (int i = 0; i < n_in; i++) {
        long long s = in_sizes[i];
        if (s == 128 || s == 512) {
            b = (const float*)d_in[i];
        } else if (s == 16384 || s == 65536) {
            W = (const float*)d_in[i];
        } else if (s == 625000 || s == 1250000 || s == 2500000 || s == 5000000) {
            if (n_idx < 2) idx_words[n_idx++] = (const int*)d_in[i];
        } else if (s == 6400000 || s == 25600000) {
            feature = (const float*)d_in[i];
        }
    }
    if (!feature || !W || !b || n_idx < 2) {  // positional fallback
        feature      = (const float*)d_in[0];
        idx_words[0] = (const int*)d_in[1];
        idx_words[1] = (const int*)d_in[2];
        W            = (const float*)d_in[3];
        b            = (const float*)d_in[4];
    }

    const int N = MAX_NODES;
    const int E = MAX_EDGES;
    float* out = (float*)d_out;

    // Sort chain
    zero_counts_kernel<<<(N + 255) / 256, 256>>>();
    detect_idx_width_kernel<<<1, 32>>>(idx_words[0], idx_words[1]);
    normalize_hist_kernel<<<(E + 255) / 256, 256>>>(idx_words[0], idx_words[1], E);
    scan1_kernel<<<NUM_SCAN_BLOCKS, SCAN_BLK>>>();
    scan2_kernel<<<1, SCAN_BLK>>>();
    scan3_kernel<<<(N + 255) / 256, 256>>>();
    fill_kernel<<<(E + 255) / 256, 256>>>(E);
    // Transform (f32x2 packed math)
    gemm_kernel<<<(N + TILE_ROWS - 1) / TILE_ROWS, 256>>>(feature, W, N);
    // Atomic-free segmented reduction + bias
    reduce_kernel<<<(N * 32 + 255) / 256, 256>>>(b, out, N);
}